// round 2
// baseline (speedup 1.0000x reference)
#include <cuda_runtime.h>
#include <math.h>

#define T_LEN 2048
#define NB    256
#define DMOD  64
#define H_OUT 720
#define NBINS 1024
#define TP 16
#define TC 16
#define MAX_TILES 130

struct Meta { int P[2]; int cols[2]; float wgt[2]; };
__device__ Meta  g_meta;
__device__ float g_partial[NB * NBINS];   // per-batch |X[k]|, k=1..1024
__device__ float g_amp[NBINS];
__device__ float g_y[NB * T_LEN];

// ---------------------------------------------------------------------------
// 1) Per-batch 2048-pt complex FFT (real input), write |X[1..1024]|
// ---------------------------------------------------------------------------
__global__ void fft_kernel(const float* __restrict__ x) {
    __shared__ float2 s[T_LEN];
    int b = blockIdx.x, tid = threadIdx.x;
    const float* xb = x + (size_t)b * T_LEN;
    for (int i = tid; i < T_LEN; i += blockDim.x) {
        int rev = __brev((unsigned)i) >> 21;   // 11-bit reverse
        s[rev] = make_float2(xb[i], 0.f);
    }
    __syncthreads();
    for (int m = 2; m <= T_LEN; m <<= 1) {
        int half = m >> 1;
        float base = -6.283185307179586f / (float)m;
        for (int k = tid; k < T_LEN / 2; k += blockDim.x) {
            int j  = k & (half - 1);
            int i0 = ((k / half) * m) + j;
            int i1 = i0 + half;
            float sa, ca;
            __sincosf(base * (float)j, &sa, &ca);
            float2 u = s[i0], v = s[i1];
            float tr = ca * v.x - sa * v.y;
            float ti = ca * v.y + sa * v.x;
            s[i1] = make_float2(u.x - tr, u.y - ti);
            s[i0] = make_float2(u.x + tr, u.y + ti);
        }
        __syncthreads();
    }
    for (int k = 1 + tid; k <= NBINS; k += blockDim.x) {
        float2 v = s[k];
        g_partial[(size_t)b * NBINS + (k - 1)] = sqrtf(v.x * v.x + v.y * v.y);
    }
}

// Deterministic batch-mean reduction (no float atomics -> stable top-k)
__global__ void reduce_amp_kernel() {
    int k = blockIdx.x * blockDim.x + threadIdx.x;
    if (k >= NBINS) return;
    float acc = 0.f;
    for (int b = 0; b < NB; b++) acc += g_partial[(size_t)b * NBINS + k];
    g_amp[k] = acc * (1.f / (float)NB);
}

// ---------------------------------------------------------------------------
// 2) Top-2 bins -> periods, cols, softmax weights
// ---------------------------------------------------------------------------
__global__ void top2_kernel() {
    __shared__ float sv[NBINS];
    __shared__ int   si[NBINS];
    __shared__ float b_v; __shared__ int b_i;
    int tid = threadIdx.x;

    sv[tid] = g_amp[tid]; si[tid] = tid;
    __syncthreads();
    for (int s = NBINS / 2; s > 0; s >>= 1) {
        if (tid < s) {
            float v2 = sv[tid + s]; int i2 = si[tid + s];
            if (v2 > sv[tid] || (v2 == sv[tid] && i2 < si[tid])) { sv[tid] = v2; si[tid] = i2; }
        }
        __syncthreads();
    }
    if (tid == 0) { b_v = sv[0]; b_i = si[0]; }
    __syncthreads();
    float v1 = b_v; int i1 = b_i;
    __syncthreads();

    sv[tid] = (tid == i1) ? -1e30f : g_amp[tid]; si[tid] = tid;
    __syncthreads();
    for (int s = NBINS / 2; s > 0; s >>= 1) {
        if (tid < s) {
            float v2 = sv[tid + s]; int i2 = si[tid + s];
            if (v2 > sv[tid] || (v2 == sv[tid] && i2 < si[tid])) { sv[tid] = v2; si[tid] = i2; }
        }
        __syncthreads();
    }
    if (tid == 0) {
        float v2 = sv[0]; int i2 = si[0];
        int f1 = i1 + 1, f2 = i2 + 1;
        int P1 = (int)llrint((double)T_LEN / (double)f1); if (P1 < 1) P1 = 1;
        int P2 = (int)llrint((double)T_LEN / (double)f2); if (P2 < 1) P2 = 1;
        g_meta.P[0] = P1; g_meta.cols[0] = (T_LEN + P1 - 1) / P1;
        g_meta.P[1] = P2; g_meta.cols[1] = (T_LEN + P2 - 1) / P2;
        // softmax over (v1 >= v2)
        float e2 = __expf(v2 - v1);
        float inv = 1.f / (1.f + e2);
        g_meta.wgt[0] = inv;
        g_meta.wgt[1] = e2 * inv;
    }
}

// ---------------------------------------------------------------------------
// 3) Fused conv1(1->64) -> GELU -> conv2(64->1), tiled 16x16, per period
// ---------------------------------------------------------------------------
__device__ __forceinline__ float gelu_tanh(float v) {
    float u = 0.7978845608028654f * (v + 0.044715f * v * v * v);
    return 0.5f * v * (1.f + tanhf(u));
}

__global__ void conv_fused_kernel(const float* __restrict__ x,
                                  const float* __restrict__ w1,
                                  const float* __restrict__ b1,
                                  const float* __restrict__ w2,
                                  const float* __restrict__ b2,
                                  int period) {
    __shared__ float xs[20][20];
    __shared__ float w1s[DMOD][9];
    __shared__ float w2s[DMOD][9];
    __shared__ float b1s[DMOD];
    __shared__ float b2s;
    extern __shared__ float hs[];   // [64][18][19]

    const int P    = g_meta.P[period];
    const int cols = g_meta.cols[period];
    const float wgt = g_meta.wgt[period];

    const int ntp = (P + TP - 1) / TP;
    const int ntc = (cols + TC - 1) / TC;
    const int tile = blockIdx.x;
    if (tile >= ntp * ntc) return;

    const int b   = blockIdx.y;
    const int tp0 = (tile % ntp) * TP;
    const int tc0 = (tile / ntp) * TC;
    const int tid = threadIdx.x;    // 256

    // FIX (R1 bug): grid-stride weight staging — 576 > blockDim
    for (int i = tid; i < DMOD * 9; i += 256) {
        w1s[i / 9][i % 9] = w1[i];
        w2s[i / 9][i % 9] = w2[i];
    }
    if (tid < DMOD) b1s[tid] = b1[tid];
    if (tid == 0)   b2s = b2[0];

    // load x halo region (20x20)
    for (int i = tid; i < 400; i += 256) {
        int q = i / 20, r = i % 20;
        int p = tp0 - 2 + q, c = tc0 - 2 + r;
        float v = 0.f;
        if (p >= 0 && p < P && c >= 0 && c < cols) {
            int n = c * P + p;
            if (n < T_LEN) v = x[(size_t)b * T_LEN + n];
        }
        xs[q][r] = v;
    }
    __syncthreads();

    // conv1 + GELU -> h tile (18x18 per channel)
    const int HW = 18 * 18;
    for (int i = tid; i < DMOD * HW; i += 256) {
        int ch = i / HW, pos = i - ch * HW;
        int hp = pos / 18, hc = pos - hp * 18;
        int p = tp0 - 1 + hp, c = tc0 - 1 + hc;
        float hv = 0.f;
        if (p >= 0 && p < P && c >= 0 && c < cols) {
            float acc = b1s[ch];
            #pragma unroll
            for (int dp = 0; dp < 3; dp++)
                #pragma unroll
                for (int dc = 0; dc < 3; dc++)
                    acc = fmaf(w1s[ch][dp * 3 + dc], xs[hp + dp][hc + dc], acc);
            hv = gelu_tanh(acc);
        }
        hs[(ch * 18 + hp) * 19 + hc] = hv;
    }
    __syncthreads();

    // conv2 -> one output per thread
    int op = tid / TC, oc = tid % TC;
    int p = tp0 + op, c = tc0 + oc;
    if (p < P && c < cols) {
        int n = c * P + p;
        if (n < T_LEN) {
            float acc = b2s;
            #pragma unroll 4
            for (int ch = 0; ch < DMOD; ch++) {
                const float* hrow = &hs[(ch * 18 + op) * 19 + oc];
                #pragma unroll
                for (int dp = 0; dp < 3; dp++)
                    #pragma unroll
                    for (int dc = 0; dc < 3; dc++)
                        acc = fmaf(w2s[ch][dp * 3 + dc], hrow[dp * 19 + dc], acc);
            }
            size_t oidx = (size_t)b * T_LEN + n;
            if (period == 0) g_y[oidx] = wgt * acc;
            else             g_y[oidx] += wgt * acc;
        }
    }
}

// ---------------------------------------------------------------------------
// 4) Head GEMM: out[256,720] = y[256,2048] @ head_w[720,2048]^T + head_b
// ---------------------------------------------------------------------------
#define BM 64
#define BN 64
#define BK 16
__global__ void head_gemm_kernel(const float* __restrict__ hw,
                                 const float* __restrict__ hb,
                                 float* __restrict__ out) {
    __shared__ float As[BK][BM + 1];
    __shared__ float Bs[BK][BN + 1];
    int tid = threadIdx.x;                 // 256
    int m0 = blockIdx.y * BM, n0 = blockIdx.x * BN;
    int tm = (tid / 16) * 4, tn = (tid % 16) * 4;
    float acc[4][4];
    #pragma unroll
    for (int i = 0; i < 4; i++)
        #pragma unroll
        for (int j = 0; j < 4; j++) acc[i][j] = 0.f;

    for (int k0 = 0; k0 < T_LEN; k0 += BK) {
        for (int i = tid; i < BM * BK; i += 256) {
            int m = i / BK, k = i % BK;
            As[k][m] = g_y[(size_t)(m0 + m) * T_LEN + k0 + k];
        }
        for (int i = tid; i < BN * BK; i += 256) {
            int n = i / BK, k = i % BK;
            Bs[k][n] = (n0 + n < H_OUT) ? hw[(size_t)(n0 + n) * T_LEN + k0 + k] : 0.f;
        }
        __syncthreads();
        #pragma unroll
        for (int k = 0; k < BK; k++) {
            float a[4], bb[4];
            #pragma unroll
            for (int r = 0; r < 4; r++) { a[r] = As[k][tm + r]; bb[r] = Bs[k][tn + r]; }
            #pragma unroll
            for (int i = 0; i < 4; i++)
                #pragma unroll
                for (int j = 0; j < 4; j++)
                    acc[i][j] = fmaf(a[i], bb[j], acc[i][j]);
        }
        __syncthreads();
    }
    #pragma unroll
    for (int i = 0; i < 4; i++)
        #pragma unroll
        for (int j = 0; j < 4; j++) {
            int m = m0 + tm + i, n = n0 + tn + j;
            if (n < H_OUT) out[(size_t)m * H_OUT + n] = acc[i][j] + hb[n];
        }
}

// ---------------------------------------------------------------------------
extern "C" void kernel_launch(void* const* d_in, const int* in_sizes, int n_in,
                              void* d_out, int out_size) {
    const float* x  = (const float*)d_in[0];
    const float* w1 = (const float*)d_in[1];
    const float* b1 = (const float*)d_in[2];
    const float* w2 = (const float*)d_in[3];
    const float* b2 = (const float*)d_in[4];
    const float* hw = (const float*)d_in[5];
    const float* hb = (const float*)d_in[6];
    float* out = (float*)d_out;

    const int HS_BYTES = DMOD * 18 * 19 * (int)sizeof(float);   // 87552
    static int smem_set = 0;
    if (!smem_set) {
        cudaFuncSetAttribute(conv_fused_kernel,
                             cudaFuncAttributeMaxDynamicSharedMemorySize, HS_BYTES);
        smem_set = 1;
    }

    fft_kernel<<<NB, 256>>>(x);
    reduce_amp_kernel<<<NBINS / 256, 256>>>();
    top2_kernel<<<1, NBINS>>>();
    conv_fused_kernel<<<dim3(MAX_TILES, NB), 256, HS_BYTES>>>(x, w1, b1, w2, b2, 0);
    conv_fused_kernel<<<dim3(MAX_TILES, NB), 256, HS_BYTES>>>(x, w1, b1, w2, b2, 1);
    head_gemm_kernel<<<dim3((H_OUT + BN - 1) / BN, NB / BM), 256>>>(hw, hb, out);
}

// round 3
// speedup vs baseline: 2.2036x; 2.2036x over previous
#include <cuda_runtime.h>
#include <math.h>

#define T_LEN 2048
#define NB    256
#define DMOD  64
#define H_OUT 720
#define NBINS 1024
#define TO 14              // output tile (14x14)
#define HT 16              // h tile with halo (16x16) = 256 = blockDim
#define XT 18              // x tile with halo (18x18)
#define CH 32              // channel chunk
#define MAX_TILES 150

struct Meta { int P[2]; int cols[2]; float wgt[2]; };
__device__ Meta  g_meta;
__device__ float g_partial[NB * NBINS];
__device__ float g_amp[NBINS];
__device__ float g_y[NB * T_LEN];

// ---------------------------------------------------------------------------
// 1) Per-batch 2048-pt complex FFT, write |X[1..1024]|
// ---------------------------------------------------------------------------
__global__ void fft_kernel(const float* __restrict__ x) {
    __shared__ float2 s[T_LEN];
    int b = blockIdx.x, tid = threadIdx.x;
    const float* xb = x + (size_t)b * T_LEN;
    for (int i = tid; i < T_LEN; i += blockDim.x) {
        int rev = __brev((unsigned)i) >> 21;
        s[rev] = make_float2(xb[i], 0.f);
    }
    __syncthreads();
    for (int m = 2; m <= T_LEN; m <<= 1) {
        int half = m >> 1;
        float base = -6.283185307179586f / (float)m;
        for (int k = tid; k < T_LEN / 2; k += blockDim.x) {
            int j  = k & (half - 1);
            int i0 = ((k / half) * m) + j;
            int i1 = i0 + half;
            float sa, ca;
            __sincosf(base * (float)j, &sa, &ca);
            float2 u = s[i0], v = s[i1];
            float tr = ca * v.x - sa * v.y;
            float ti = ca * v.y + sa * v.x;
            s[i1] = make_float2(u.x - tr, u.y - ti);
            s[i0] = make_float2(u.x + tr, u.y + ti);
        }
        __syncthreads();
    }
    for (int k = 1 + tid; k <= NBINS; k += blockDim.x) {
        float2 v = s[k];
        g_partial[(size_t)b * NBINS + (k - 1)] = sqrtf(v.x * v.x + v.y * v.y);
    }
}

__global__ void reduce_amp_kernel() {
    int k = blockIdx.x * blockDim.x + threadIdx.x;
    if (k >= NBINS) return;
    float acc = 0.f;
    #pragma unroll 8
    for (int b = 0; b < NB; b++) acc += g_partial[(size_t)b * NBINS + k];
    g_amp[k] = acc * (1.f / (float)NB);
}

// ---------------------------------------------------------------------------
// 2) Top-2 bins -> periods, cols, softmax weights
// ---------------------------------------------------------------------------
__global__ void top2_kernel() {
    __shared__ float sv[NBINS];
    __shared__ int   si[NBINS];
    __shared__ float b_v; __shared__ int b_i;
    int tid = threadIdx.x;

    sv[tid] = g_amp[tid]; si[tid] = tid;
    __syncthreads();
    for (int s = NBINS / 2; s > 0; s >>= 1) {
        if (tid < s) {
            float v2 = sv[tid + s]; int i2 = si[tid + s];
            if (v2 > sv[tid] || (v2 == sv[tid] && i2 < si[tid])) { sv[tid] = v2; si[tid] = i2; }
        }
        __syncthreads();
    }
    if (tid == 0) { b_v = sv[0]; b_i = si[0]; }
    __syncthreads();
    float v1 = b_v; int i1 = b_i;
    __syncthreads();

    sv[tid] = (tid == i1) ? -1e30f : g_amp[tid]; si[tid] = tid;
    __syncthreads();
    for (int s = NBINS / 2; s > 0; s >>= 1) {
        if (tid < s) {
            float v2 = sv[tid + s]; int i2 = si[tid + s];
            if (v2 > sv[tid] || (v2 == sv[tid] && i2 < si[tid])) { sv[tid] = v2; si[tid] = i2; }
        }
        __syncthreads();
    }
    if (tid == 0) {
        float v2 = sv[0]; int i2 = si[0];
        int f1 = i1 + 1, f2 = i2 + 1;
        int P1 = (int)llrint((double)T_LEN / (double)f1); if (P1 < 1) P1 = 1;
        int P2 = (int)llrint((double)T_LEN / (double)f2); if (P2 < 1) P2 = 1;
        g_meta.P[0] = P1; g_meta.cols[0] = (T_LEN + P1 - 1) / P1;
        g_meta.P[1] = P2; g_meta.cols[1] = (T_LEN + P2 - 1) / P2;
        float e2 = __expf(v2 - v1);
        float inv = 1.f / (1.f + e2);
        g_meta.wgt[0] = inv;
        g_meta.wgt[1] = e2 * inv;
    }
}

// ---------------------------------------------------------------------------
// 3) Fused conv1 -> GELU -> conv2, tile 14x14 out / 16x16 h / 18x18 x
// ---------------------------------------------------------------------------
__device__ __forceinline__ float gelu_fast(float v) {
    float v2 = v * v;
    float u  = v * fmaf(0.035677408136f, v2, 0.7978845608f);
    float t;
    asm("tanh.approx.f32 %0, %1;" : "=f"(t) : "f"(u));
    return v * fmaf(0.5f, t, 0.5f);
}

__global__ __launch_bounds__(256) void conv_fused_kernel(
        const float* __restrict__ x,
        const float* __restrict__ w1,
        const float* __restrict__ b1,
        const float* __restrict__ w2,
        const float* __restrict__ b2,
        int period) {
    __shared__ float xs[XT][XT];
    __shared__ __align__(16) float w1p[DMOD][12];
    __shared__ __align__(16) float w2p[DMOD][12];
    __shared__ float b1s[DMOD];
    __shared__ float b2s_s;
    extern __shared__ float hs[];        // [CH][HT][HT+1]

    const int P    = g_meta.P[period];
    const int cols = g_meta.cols[period];
    const float wgt = g_meta.wgt[period];

    const int ntp = (P + TO - 1) / TO;
    const int ntc = (cols + TO - 1) / TO;
    const int tile = blockIdx.x;
    if (tile >= ntp * ntc) return;

    const int b   = blockIdx.y;
    const int tp0 = (tile % ntp) * TO;
    const int tc0 = (tile / ntp) * TO;
    const int tid = threadIdx.x;         // 256

    // stage weights (padded rows of 12 for float4 loads)
    for (int i = tid; i < DMOD * 9; i += 256) {
        int ch = i / 9, j = i - ch * 9;
        w1p[ch][j] = w1[i];
        w2p[ch][j] = w2[i];
    }
    for (int i = tid; i < DMOD * 3; i += 256) {      // zero the pad lanes
        int ch = i / 3, j = 9 + (i - ch * 3);
        w1p[ch][j] = 0.f; w2p[ch][j] = 0.f;
    }
    if (tid < DMOD) b1s[tid] = b1[tid];
    if (tid == 0)   b2s_s = b2[0];

    // load x halo (18x18), origin (tp0-2, tc0-2); zeros outside P x cols grid
    for (int i = tid; i < XT * XT; i += 256) {
        int q = i / XT, r = i - q * XT;
        int p = tp0 - 2 + q, c = tc0 - 2 + r;
        float v = 0.f;
        if (p >= 0 && p < P && c >= 0 && c < cols) {
            int n = c * P + p;
            if (n < T_LEN) v = x[(size_t)b * T_LEN + n];
        }
        xs[q][r] = v;
    }
    __syncthreads();

    // ---- per-thread h position (one each, 16x16 = 256) ----
    const int hp = tid >> 4, hc = tid & 15;          // h tile coords
    const int gp = tp0 - 1 + hp, gc = tc0 - 1 + hc;  // grid coords of h point
    const bool hvalid = (gp >= 0 && gp < P && gc >= 0 && gc < cols);

    // x registers for this h position (persist across all channels)
    float x00 = xs[hp + 0][hc + 0], x01 = xs[hp + 0][hc + 1], x02 = xs[hp + 0][hc + 2];
    float x10 = xs[hp + 1][hc + 0], x11 = xs[hp + 1][hc + 1], x12 = xs[hp + 1][hc + 2];
    float x20 = xs[hp + 2][hc + 0], x21 = xs[hp + 2][hc + 1], x22 = xs[hp + 2][hc + 2];

    // ---- per-thread output position (tid < 196) ----
    const int op = tid / TO, oc = tid - op * TO;     // 0..13 when tid<196
    bool outv = false; int on = 0;
    if (tid < TO * TO) {
        int p = tp0 + op, c = tc0 + oc;
        if (p < P && c < cols) {
            int n = c * P + p;
            if (n < T_LEN) { outv = true; on = n; }
        }
    }
    float acc = b2s_s;
    const int HROW = HT + 1;                         // 17
    const int HPL  = HT * HROW;                      // per-channel plane

    for (int c0 = 0; c0 < DMOD; c0 += CH) {
        // produce: h for channels [c0, c0+CH)
        #pragma unroll 4
        for (int lch = 0; lch < CH; lch++) {
            int ch = c0 + lch;
            float hv = 0.f;
            if (hvalid) {
                const float4* wr = (const float4*)w1p[ch];
                float4 wa = wr[0], wb = wr[1], wc = wr[2];
                float a = b1s[ch];
                a = fmaf(wa.x, x00, a); a = fmaf(wa.y, x01, a); a = fmaf(wa.z, x02, a);
                a = fmaf(wa.w, x10, a); a = fmaf(wb.x, x11, a); a = fmaf(wb.y, x12, a);
                a = fmaf(wb.z, x20, a); a = fmaf(wb.w, x21, a); a = fmaf(wc.x, x22, a);
                hv = gelu_fast(a);
            }
            hs[lch * HPL + hp * HROW + hc] = hv;
        }
        __syncthreads();

        // consume: conv2 partial accumulation over this chunk
        if (outv) {
            #pragma unroll 4
            for (int lch = 0; lch < CH; lch++) {
                const float4* wr = (const float4*)w2p[c0 + lch];
                float4 wa = wr[0], wb = wr[1], wc = wr[2];
                const float* hr = &hs[lch * HPL + op * HROW + oc];
                acc = fmaf(wa.x, hr[0],         acc);
                acc = fmaf(wa.y, hr[1],         acc);
                acc = fmaf(wa.z, hr[2],         acc);
                acc = fmaf(wa.w, hr[HROW],      acc);
                acc = fmaf(wb.x, hr[HROW + 1],  acc);
                acc = fmaf(wb.y, hr[HROW + 2],  acc);
                acc = fmaf(wb.z, hr[2*HROW],    acc);
                acc = fmaf(wb.w, hr[2*HROW + 1], acc);
                acc = fmaf(wc.x, hr[2*HROW + 2], acc);
            }
        }
        __syncthreads();
    }

    if (outv) {
        size_t oidx = (size_t)b * T_LEN + on;
        if (period == 0) g_y[oidx] = wgt * acc;
        else             g_y[oidx] += wgt * acc;
    }
}

// ---------------------------------------------------------------------------
// 4) Head GEMM: out[256,720] = y @ head_w^T + head_b   (BM=32,BN=48 -> 120 blocks)
// ---------------------------------------------------------------------------
#define BM 32
#define BN 48
#define BK 32
__global__ __launch_bounds__(256) void head_gemm_kernel(
        const float* __restrict__ hw,
        const float* __restrict__ hb,
        float* __restrict__ out) {
    __shared__ float As[BK][BM + 1];
    __shared__ float Bs[BK][BN + 1];
    int tid = threadIdx.x;
    int m0 = blockIdx.y * BM, n0 = blockIdx.x * BN;
    int tm = (tid / 16) * 2, tn = (tid % 16) * 3;    // 2x3 per thread
    float acc[2][3] = {{0.f,0.f,0.f},{0.f,0.f,0.f}};

    for (int k0 = 0; k0 < T_LEN; k0 += BK) {
        for (int i = tid; i < BM * BK; i += 256) {
            int m = i / BK, k = i % BK;
            As[k][m] = g_y[(size_t)(m0 + m) * T_LEN + k0 + k];
        }
        for (int i = tid; i < BN * BK; i += 256) {
            int n = i / BK, k = i % BK;
            Bs[k][n] = hw[(size_t)(n0 + n) * T_LEN + k0 + k];
        }
        __syncthreads();
        #pragma unroll
        for (int k = 0; k < BK; k++) {
            float a0 = As[k][tm], a1 = As[k][tm + 1];
            float b0 = Bs[k][tn], b1 = Bs[k][tn + 1], b2v = Bs[k][tn + 2];
            acc[0][0] = fmaf(a0, b0, acc[0][0]);
            acc[0][1] = fmaf(a0, b1, acc[0][1]);
            acc[0][2] = fmaf(a0, b2v, acc[0][2]);
            acc[1][0] = fmaf(a1, b0, acc[1][0]);
            acc[1][1] = fmaf(a1, b1, acc[1][1]);
            acc[1][2] = fmaf(a1, b2v, acc[1][2]);
        }
        __syncthreads();
    }
    #pragma unroll
    for (int i = 0; i < 2; i++)
        #pragma unroll
        for (int j = 0; j < 3; j++) {
            int m = m0 + tm + i, n = n0 + tn + j;
            out[(size_t)m * H_OUT + n] = acc[i][j] + hb[n];
        }
}

// ---------------------------------------------------------------------------
extern "C" void kernel_launch(void* const* d_in, const int* in_sizes, int n_in,
                              void* d_out, int out_size) {
    const float* x  = (const float*)d_in[0];
    const float* w1 = (const float*)d_in[1];
    const float* b1 = (const float*)d_in[2];
    const float* w2 = (const float*)d_in[3];
    const float* b2 = (const float*)d_in[4];
    const float* hw = (const float*)d_in[5];
    const float* hb = (const float*)d_in[6];
    float* out = (float*)d_out;

    const int HS_BYTES = CH * HT * (HT + 1) * (int)sizeof(float);  // 34816
    static int smem_set = 0;
    if (!smem_set) {
        cudaFuncSetAttribute(conv_fused_kernel,
                             cudaFuncAttributeMaxDynamicSharedMemorySize, HS_BYTES);
        smem_set = 1;
    }

    fft_kernel<<<NB, 256>>>(x);
    reduce_amp_kernel<<<NBINS / 256, 256>>>();
    top2_kernel<<<1, NBINS>>>();
    conv_fused_kernel<<<dim3(MAX_TILES, NB), 256, HS_BYTES>>>(x, w1, b1, w2, b2, 0);
    conv_fused_kernel<<<dim3(MAX_TILES, NB), 256, HS_BYTES>>>(x, w1, b1, w2, b2, 1);
    head_gemm_kernel<<<dim3(H_OUT / BN, NB / BM), 256>>>(hw, hb, out);
}

// round 5
// speedup vs baseline: 2.6609x; 1.2075x over previous
#include <cuda_runtime.h>
#include <math.h>

#define T_LEN 2048
#define NB    256
#define DMOD  64
#define H_OUT 720
#define NBINS 1024
#define PMAX1 40              // 1D kernel handles P <= 40; 2D fallback above
#define SPMAX 44              // align4(PMAX1+2)
#define SPAN  1024            // padded outputs per block (256 thr x 4)
#define CH1   8               // channel chunk (1D kernel)
#define HSTR  1116
#define XLEN  (SPAN + 4*SPMAX + 4)     // 1204
// 2D fallback tiling
#define TO 14
#define HT 16
#define XT 18
#define CH2 32
#define MAX_TILES 150

struct Meta { int P[2]; int cols[2]; float wgt[2]; };
__device__ Meta  g_meta;
__device__ float g_partial[NB * NBINS];
__device__ float g_amp[NBINS];
__device__ float g_y[NB * T_LEN];
__device__ float g_w1perm[DMOD * 9];
__device__ float g_w2perm[DMOD * 9];

// ---------------------------------------------------------------------------
// 1) Per-batch 2048-pt complex FFT, write |X[1..1024]|
// ---------------------------------------------------------------------------
__global__ void fft_kernel(const float* __restrict__ x) {
    __shared__ float2 s[T_LEN];
    int b = blockIdx.x, tid = threadIdx.x;
    const float* xb = x + (size_t)b * T_LEN;
    for (int i = tid; i < T_LEN; i += blockDim.x) {
        int rev = __brev((unsigned)i) >> 21;
        s[rev] = make_float2(xb[i], 0.f);
    }
    __syncthreads();
    for (int m = 2; m <= T_LEN; m <<= 1) {
        int half = m >> 1;
        float base = -6.283185307179586f / (float)m;
        for (int k = tid; k < T_LEN / 2; k += blockDim.x) {
            int j  = k & (half - 1);
            int i0 = ((k / half) * m) + j;
            int i1 = i0 + half;
            float sa, ca;
            __sincosf(base * (float)j, &sa, &ca);
            float2 u = s[i0], v = s[i1];
            float tr = ca * v.x - sa * v.y;
            float ti = ca * v.y + sa * v.x;
            s[i1] = make_float2(u.x - tr, u.y - ti);
            s[i0] = make_float2(u.x + tr, u.y + ti);
        }
        __syncthreads();
    }
    for (int k = 1 + tid; k <= NBINS; k += blockDim.x) {
        float2 v = s[k];
        g_partial[(size_t)b * NBINS + (k - 1)] = sqrtf(v.x * v.x + v.y * v.y);
    }
}

__global__ void reduce_amp_kernel() {
    int k = blockIdx.x * blockDim.x + threadIdx.x;
    if (k >= NBINS) return;
    float acc = 0.f;
    #pragma unroll 8
    for (int b = 0; b < NB; b++) acc += g_partial[(size_t)b * NBINS + k];
    g_amp[k] = acc * (1.f / (float)NB);
}

// ---------------------------------------------------------------------------
// 2) Top-2 bins -> periods, cols, softmax weights
// ---------------------------------------------------------------------------
__global__ void top2_kernel() {
    __shared__ float sv[NBINS];
    __shared__ int   si[NBINS];
    __shared__ float b_v; __shared__ int b_i;
    int tid = threadIdx.x;

    sv[tid] = g_amp[tid]; si[tid] = tid;
    __syncthreads();
    for (int s = NBINS / 2; s > 0; s >>= 1) {
        if (tid < s) {
            float v2 = sv[tid + s]; int i2 = si[tid + s];
            if (v2 > sv[tid] || (v2 == sv[tid] && i2 < si[tid])) { sv[tid] = v2; si[tid] = i2; }
        }
        __syncthreads();
    }
    if (tid == 0) { b_v = sv[0]; b_i = si[0]; }
    __syncthreads();
    float v1 = b_v; int i1 = b_i;
    __syncthreads();

    sv[tid] = (tid == i1) ? -1e30f : g_amp[tid]; si[tid] = tid;
    __syncthreads();
    for (int s = NBINS / 2; s > 0; s >>= 1) {
        if (tid < s) {
            float v2 = sv[tid + s]; int i2 = si[tid + s];
            if (v2 > sv[tid] || (v2 == sv[tid] && i2 < si[tid])) { sv[tid] = v2; si[tid] = i2; }
        }
        __syncthreads();
    }
    if (tid == 0) {
        float v2 = sv[0]; int i2 = si[0];
        int f1 = i1 + 1, f2 = i2 + 1;
        int P1 = (int)llrint((double)T_LEN / (double)f1); if (P1 < 1) P1 = 1;
        int P2 = (int)llrint((double)T_LEN / (double)f2); if (P2 < 1) P2 = 1;
        g_meta.P[0] = P1; g_meta.cols[0] = (T_LEN + P1 - 1) / P1;
        g_meta.P[1] = P2; g_meta.cols[1] = (T_LEN + P2 - 1) / P2;
        float e2 = __expf(v2 - v1);
        float inv = 1.f / (1.f + e2);
        g_meta.wgt[0] = inv;
        g_meta.wgt[1] = e2 * inv;
    }
}

__device__ __forceinline__ float gelu_fast(float v) {
    float v2 = v * v;
    float u  = v * fmaf(0.035677408136f, v2, 0.7978845608f);
    float t;
    asm("tanh.approx.f32 %0, %1;" : "=f"(t) : "f"(u));
    return v * fmaf(0.5f, t, 0.5f);
}

// Weight permutation for conv1d: slot order
//   s=0..2:  dc= 0, dp=-1,0,+1
//   s=3..5:  dc=+1, dp=-1,0,+1
//   s=6..8:  dc=-1, dp=-1,0,+1
// Source layout: w[ch][dp+1][dc+1] row-major.
__global__ void permute_weights_kernel(const float* __restrict__ w1,
                                       const float* __restrict__ w2,
                                       float* __restrict__ w1o,
                                       float* __restrict__ w2o) {
    int i = blockIdx.x * blockDim.x + threadIdx.x;
    if (i >= DMOD * 9) return;
    int ch = i / 9, s = i - ch * 9;
    int dc = (s < 3) ? 0 : (s < 6 ? 1 : -1);
    int dp = (s < 3) ? (s - 1) : (s < 6 ? (s - 4) : (s - 7));
    int src = ch * 9 + (dp + 1) * 3 + (dc + 1);
    w1o[i] = w1[src];
    w2o[i] = w2[src];
}

// ---------------------------------------------------------------------------
// 3a) 1D guard-padded fused conv (P <= PMAX1)
//     padded space: column stride SP4 = align4(P+2); slot q -> c = q/SP4,
//     pr = q%SP4 - 1; valid image point iff 0 <= pr < P. Guard slots hold
//     zeros, so the 3x3 conv is a branchless 9-tap stencil at offsets
//     dc*SP4 + dp.
// ---------------------------------------------------------------------------
__global__ __launch_bounds__(256) void conv1d_kernel(
        const float* __restrict__ x,
        const float* __restrict__ w1,   // permuted
        const float* __restrict__ b1,
        const float* __restrict__ w2,   // permuted
        const float* __restrict__ b2,
        int period) {
    const int P = g_meta.P[period];
    if (P > PMAX1) return;
    const int cols = g_meta.cols[period];
    const float wgt = g_meta.wgt[period];
    const int SP4  = (P + 2 + 3) & ~3;
    const int padL = cols * SP4;

    const int q0 = blockIdx.x * SPAN;
    if (q0 >= padL) return;
    const int b   = blockIdx.y;
    const int tid = threadIdx.x;

    __shared__ float xs[XLEN];
    __shared__ __align__(16) float w1p[DMOD][12];
    __shared__ __align__(16) float w2p[DMOD][12];
    __shared__ float b1s[DMOD];
    __shared__ float b2s_s;
    extern __shared__ float hs[];           // [CH1][HSTR]

    for (int i = tid; i < DMOD * 9; i += 256) {
        int ch = i / 9, j = i - ch * 9;
        w1p[ch][j] = w1[i];
        w2p[ch][j] = w2[i];
    }
    for (int i = tid; i < DMOD * 3; i += 256) {
        int ch = i / 3, j = 9 + (i - ch * 3);
        w1p[ch][j] = 0.f; w2p[ch][j] = 0.f;
    }
    if (tid < DMOD) b1s[tid] = b1[tid];
    if (tid == 0)   b2s_s = b2[0];

    // stage x in guard-padded layout over [qx0, qx0 + XLEN)
    const int qx0 = q0 - 2 * SP4 - 2;
    const float* xb = x + (size_t)b * T_LEN;
    for (int i = tid; i < XLEN; i += 256) {
        int q = qx0 + i;
        float v = 0.f;
        if (q >= 0 && q < padL) {
            int c  = q / SP4;
            int pr = q - c * SP4 - 1;
            if (pr >= 0 && pr < P) {
                int n = c * P + pr;
                if (n < T_LEN) v = xb[n];
            }
        }
        xs[i] = v;
    }
    __syncthreads();

    // per-thread outputs: 4 consecutive padded slots
    const int qout = q0 + tid * 4;
    int  on[4]; bool ov[4]; bool anyv = false;
    #pragma unroll
    for (int r = 0; r < 4; r++) {
        int q = qout + r;
        ov[r] = false; on[r] = 0;
        if (q < padL) {
            int c  = q / SP4;
            int pr = q - c * SP4 - 1;
            if (pr >= 0 && pr < P) {
                int n = c * P + pr;
                if (n < T_LEN) { ov[r] = true; on[r] = n; anyv = true; }
            }
        }
    }
    float acc[4] = {b2s_s, b2s_s, b2s_s, b2s_s};

    const int hq0  = q0 - SP4 - 1;          // padded q of hs[.][0]
    const int hlen = SPAN + 2 * SP4 + 2;

    for (int c0 = 0; c0 < DMOD; c0 += CH1) {
        // ---- produce h for channels [c0, c0+CH1) ----
        for (int j = tid; j < hlen; j += 256) {
            int q = hq0 + j;
            bool hv = false;
            if (q >= 0 && q < padL) {
                int c  = q / SP4;
                int pr = q - c * SP4 - 1;
                hv = (pr >= 0 && pr < P);     // n>=T_LEN slots are valid (ref pads with zeros)
            }
            if (hv) {
                int xi = j + SP4 + 1;         // xs index of q
                // taps t_{dc}{dp}: value at offset dc*SP4 + dp
                float tm1m1 = xs[xi - SP4 - 1], tm10 = xs[xi - SP4], tm1p1 = xs[xi - SP4 + 1];
                float t0m1  = xs[xi - 1],       t00  = xs[xi],       t0p1  = xs[xi + 1];
                float tp1m1 = xs[xi + SP4 - 1], tp10 = xs[xi + SP4], tp1p1 = xs[xi + SP4 + 1];
                #pragma unroll
                for (int l = 0; l < CH1; l++) {
                    int ch = c0 + l;
                    const float4* wr = (const float4*)w1p[ch];
                    float4 wa = wr[0], wb4 = wr[1], wc = wr[2];
                    float a = b1s[ch];
                    // permuted slots: [dc=0: dp=-1,0,1][dc=1: dp=-1,0,1][dc=-1: dp=-1,0,1]
                    a = fmaf(wa.x,  t0m1,  a);
                    a = fmaf(wa.y,  t00,   a);
                    a = fmaf(wa.z,  t0p1,  a);
                    a = fmaf(wa.w,  tp1m1, a);
                    a = fmaf(wb4.x, tp10,  a);
                    a = fmaf(wb4.y, tp1p1, a);
                    a = fmaf(wb4.z, tm1m1, a);
                    a = fmaf(wb4.w, tm10,  a);
                    a = fmaf(wc.x,  tm1p1, a);
                    hs[l * HSTR + j] = gelu_fast(a);
                }
            } else {
                #pragma unroll
                for (int l = 0; l < CH1; l++) hs[l * HSTR + j] = 0.f;
            }
        }
        __syncthreads();

        // ---- consume: conv2 partial accumulation ----
        if (anyv) {
            const int jb = tid * 4 + SP4 + 1;   // hs index of qout
            #pragma unroll
            for (int l = 0; l < CH1; l++) {
                const float4* wr = (const float4*)w2p[c0 + l];
                float4 wa = wr[0], wb4 = wr[1], wc = wr[2];
                const float* hp = &hs[l * HSTR];
                #pragma unroll
                for (int dc = -1; dc <= 1; dc++) {
                    int base = jb + dc * SP4 - 1;      // 4-aligned
                    float4 h0 = *(const float4*)(hp + base);
                    float2 h1 = *(const float2*)(hp + base + 4);
                    float hv_[6] = {h0.x, h0.y, h0.z, h0.w, h1.x, h1.y};
                    float wm1, w0, wp1;
                    if (dc == -1)      { wm1 = wb4.z; w0 = wb4.w; wp1 = wc.x; }
                    else if (dc == 0)  { wm1 = wa.x;  w0 = wa.y;  wp1 = wa.z; }
                    else               { wm1 = wa.w;  w0 = wb4.x; wp1 = wb4.y; }
                    #pragma unroll
                    for (int r = 0; r < 4; r++) {
                        acc[r] = fmaf(wm1, hv_[r],     acc[r]);
                        acc[r] = fmaf(w0,  hv_[r + 1], acc[r]);
                        acc[r] = fmaf(wp1, hv_[r + 2], acc[r]);
                    }
                }
            }
        }
        __syncthreads();
    }

    #pragma unroll
    for (int r = 0; r < 4; r++) {
        if (ov[r]) {
            size_t oidx = (size_t)b * T_LEN + on[r];
            if (period == 0) g_y[oidx] = wgt * acc[r];
            else             g_y[oidx] += wgt * acc[r];
        }
    }
}

// ---------------------------------------------------------------------------
// 3b) 2D tiled fused conv (fallback, P > PMAX1)
// ---------------------------------------------------------------------------
__global__ __launch_bounds__(256) void conv2d_kernel(
        const float* __restrict__ x,
        const float* __restrict__ w1,
        const float* __restrict__ b1,
        const float* __restrict__ w2,
        const float* __restrict__ b2,
        int period) {
    const int P = g_meta.P[period];
    if (P <= PMAX1) return;
    __shared__ float xs2[XT][XT];
    __shared__ __align__(16) float w1p[DMOD][12];
    __shared__ __align__(16) float w2p[DMOD][12];
    __shared__ float b1s[DMOD];
    __shared__ float b2s_s;
    extern __shared__ float hs[];        // [CH2][HT][HT+1]

    const int cols = g_meta.cols[period];
    const float wgt = g_meta.wgt[period];

    const int ntp = (P + TO - 1) / TO;
    const int ntc = (cols + TO - 1) / TO;
    const int tile = blockIdx.x;
    if (tile >= ntp * ntc) return;

    const int b   = blockIdx.y;
    const int tp0 = (tile % ntp) * TO;
    const int tc0 = (tile / ntp) * TO;
    const int tid = threadIdx.x;

    for (int i = tid; i < DMOD * 9; i += 256) {
        int ch = i / 9, j = i - ch * 9;
        w1p[ch][j] = w1[i];
        w2p[ch][j] = w2[i];
    }
    for (int i = tid; i < DMOD * 3; i += 256) {
        int ch = i / 3, j = 9 + (i - ch * 3);
        w1p[ch][j] = 0.f; w2p[ch][j] = 0.f;
    }
    if (tid < DMOD) b1s[tid] = b1[tid];
    if (tid == 0)   b2s_s = b2[0];

    for (int i = tid; i < XT * XT; i += 256) {
        int q = i / XT, r = i - q * XT;
        int p = tp0 - 2 + q, c = tc0 - 2 + r;
        float v = 0.f;
        if (p >= 0 && p < P && c >= 0 && c < cols) {
            int n = c * P + p;
            if (n < T_LEN) v = x[(size_t)b * T_LEN + n];
        }
        xs2[q][r] = v;
    }
    __syncthreads();

    const int hp = tid >> 4, hc = tid & 15;
    const int gp = tp0 - 1 + hp, gc = tc0 - 1 + hc;
    const bool hvalid = (gp >= 0 && gp < P && gc >= 0 && gc < cols);

    float x00 = xs2[hp + 0][hc + 0], x01 = xs2[hp + 0][hc + 1], x02 = xs2[hp + 0][hc + 2];
    float x10 = xs2[hp + 1][hc + 0], x11 = xs2[hp + 1][hc + 1], x12 = xs2[hp + 1][hc + 2];
    float x20 = xs2[hp + 2][hc + 0], x21 = xs2[hp + 2][hc + 1], x22 = xs2[hp + 2][hc + 2];

    const int op = tid / TO, oc = tid - op * TO;
    bool outv = false; int on = 0;
    if (tid < TO * TO) {
        int p = tp0 + op, c = tc0 + oc;
        if (p < P && c < cols) {
            int n = c * P + p;
            if (n < T_LEN) { outv = true; on = n; }
        }
    }
    float acc = b2s_s;
    const int HROW = HT + 1;
    const int HPL  = HT * HROW;

    for (int c0 = 0; c0 < DMOD; c0 += CH2) {
        #pragma unroll 4
        for (int lch = 0; lch < CH2; lch++) {
            int ch = c0 + lch;
            float hv = 0.f;
            if (hvalid) {
                const float4* wr = (const float4*)w1p[ch];
                float4 wa = wr[0], wb = wr[1], wc = wr[2];
                float a = b1s[ch];
                a = fmaf(wa.x, x00, a); a = fmaf(wa.y, x01, a); a = fmaf(wa.z, x02, a);
                a = fmaf(wa.w, x10, a); a = fmaf(wb.x, x11, a); a = fmaf(wb.y, x12, a);
                a = fmaf(wb.z, x20, a); a = fmaf(wb.w, x21, a); a = fmaf(wc.x, x22, a);
                hv = gelu_fast(a);
            }
            hs[lch * HPL + hp * HROW + hc] = hv;
        }
        __syncthreads();

        if (outv) {
            #pragma unroll 4
            for (int lch = 0; lch < CH2; lch++) {
                const float4* wr = (const float4*)w2p[c0 + lch];
                float4 wa = wr[0], wb = wr[1], wc = wr[2];
                const float* hr = &hs[lch * HPL + op * HROW + oc];
                acc = fmaf(wa.x, hr[0],          acc);
                acc = fmaf(wa.y, hr[1],          acc);
                acc = fmaf(wa.z, hr[2],          acc);
                acc = fmaf(wa.w, hr[HROW],       acc);
                acc = fmaf(wb.x, hr[HROW + 1],   acc);
                acc = fmaf(wb.y, hr[HROW + 2],   acc);
                acc = fmaf(wb.z, hr[2*HROW],     acc);
                acc = fmaf(wb.w, hr[2*HROW + 1], acc);
                acc = fmaf(wc.x, hr[2*HROW + 2], acc);
            }
        }
        __syncthreads();
    }

    if (outv) {
        size_t oidx = (size_t)b * T_LEN + on;
        if (period == 0) g_y[oidx] = wgt * acc;
        else             g_y[oidx] += wgt * acc;
    }
}

// ---------------------------------------------------------------------------
// 4) Head GEMM
// ---------------------------------------------------------------------------
#define BM 32
#define BN 48
#define BK 32
__global__ __launch_bounds__(256) void head_gemm_kernel(
        const float* __restrict__ hw,
        const float* __restrict__ hb,
        float* __restrict__ out) {
    __shared__ float As[BK][BM + 1];
    __shared__ float Bs[BK][BN + 1];
    int tid = threadIdx.x;
    int m0 = blockIdx.y * BM, n0 = blockIdx.x * BN;
    int tm = (tid / 16) * 2, tn = (tid % 16) * 3;
    float acc[2][3] = {{0.f,0.f,0.f},{0.f,0.f,0.f}};

    for (int k0 = 0; k0 < T_LEN; k0 += BK) {
        for (int i = tid; i < BM * BK; i += 256) {
            int m = i / BK, k = i % BK;
            As[k][m] = g_y[(size_t)(m0 + m) * T_LEN + k0 + k];
        }
        for (int i = tid; i < BN * BK; i += 256) {
            int n = i / BK, k = i % BK;
            Bs[k][n] = hw[(size_t)(n0 + n) * T_LEN + k0 + k];
        }
        __syncthreads();
        #pragma unroll
        for (int k = 0; k < BK; k++) {
            float a0 = As[k][tm], a1 = As[k][tm + 1];
            float b0 = Bs[k][tn], b1 = Bs[k][tn + 1], b2v = Bs[k][tn + 2];
            acc[0][0] = fmaf(a0, b0, acc[0][0]);
            acc[0][1] = fmaf(a0, b1, acc[0][1]);
            acc[0][2] = fmaf(a0, b2v, acc[0][2]);
            acc[1][0] = fmaf(a1, b0, acc[1][0]);
            acc[1][1] = fmaf(a1, b1, acc[1][1]);
            acc[1][2] = fmaf(a1, b2v, acc[1][2]);
        }
        __syncthreads();
    }
    #pragma unroll
    for (int i = 0; i < 2; i++)
        #pragma unroll
        for (int j = 0; j < 3; j++) {
            int m = m0 + tm + i, n = n0 + tn + j;
            out[(size_t)m * H_OUT + n] = acc[i][j] + hb[n];
        }
}

// ---------------------------------------------------------------------------
extern "C" void kernel_launch(void* const* d_in, const int* in_sizes, int n_in,
                              void* d_out, int out_size) {
    const float* x  = (const float*)d_in[0];
    const float* w1 = (const float*)d_in[1];
    const float* b1 = (const float*)d_in[2];
    const float* w2 = (const float*)d_in[3];
    const float* b2 = (const float*)d_in[4];
    const float* hw = (const float*)d_in[5];
    const float* hb = (const float*)d_in[6];
    float* out = (float*)d_out;

    const int HS1_BYTES = CH1 * HSTR * (int)sizeof(float);          // 35712
    const int HS2_BYTES = CH2 * HT * (HT + 1) * (int)sizeof(float); // 34816
    static int smem_set = 0;
    if (!smem_set) {
        cudaFuncSetAttribute(conv1d_kernel,
                             cudaFuncAttributeMaxDynamicSharedMemorySize, HS1_BYTES);
        cudaFuncSetAttribute(conv2d_kernel,
                             cudaFuncAttributeMaxDynamicSharedMemorySize, HS2_BYTES);
        smem_set = 1;
    }

    float* w1p; float* w2p;
    cudaGetSymbolAddress((void**)&w1p, g_w1perm);
    cudaGetSymbolAddress((void**)&w2p, g_w2perm);

    fft_kernel<<<NB, 256>>>(x);
    reduce_amp_kernel<<<NBINS / 256, 256>>>();
    top2_kernel<<<1, NBINS>>>();
    permute_weights_kernel<<<3, 256>>>(w1, w2, w1p, w2p);
    // period 0 writers strictly before period 1 accumulators (stream order)
    conv1d_kernel<<<dim3(8, NB), 256, HS1_BYTES>>>(x, w1p, b1, w2p, b2, 0);
    conv2d_kernel<<<dim3(MAX_TILES, NB), 256, HS2_BYTES>>>(x, w1, b1, w2, b2, 0);
    conv1d_kernel<<<dim3(8, NB), 256, HS1_BYTES>>>(x, w1p, b1, w2p, b2, 1);
    conv2d_kernel<<<dim3(MAX_TILES, NB), 256, HS2_BYTES>>>(x, w1, b1, w2, b2, 1);
    head_gemm_kernel<<<dim3(H_OUT / BN, NB / BM), 256>>>(hw, hb, out);
}